// round 10
// baseline (speedup 1.0000x reference)
#include <cuda_runtime.h>
#include <math.h>

// Problem constants
#define HW    4096
#define WIDTH 64
#define BATCH 4

// Scratch (device globals — no allocation allowed in kernel_launch)
// g_qkv: interleaved-by-4 layout (B, 192, HW, 4): channel c of pixel p at
//        ((b*192 + (c>>2))*HW + p)*4 + (c&3)
static __device__ float g_qkv[(size_t)BATCH * 768 * HW];
static __device__ float g_att[(size_t)BATCH * 256 * HW];   // channel-major, tf32-rounded
static __device__ float g_xr[(size_t)BATCH * 256 * HW];    // tf32-rounded x
static __device__ float g_wqkv[768 * 256];                 // tf32-rounded qkv_w
static __device__ float g_wproj[256 * 256];                // tf32-rounded proj_w

// ---------------------------------------------------------------------------
__device__ __forceinline__ float tf32r(float x) {
    unsigned u;
    asm("cvt.rna.tf32.f32 %0, %1;" : "=r"(u) : "f"(x));
    return __uint_as_float(u);
}

__global__ void round_tf32_copy(const float* __restrict__ in,
                                float* __restrict__ out, int n4)
{
    int i = blockIdx.x * blockDim.x + threadIdx.x;
    if (i < n4) {
        float4 v = ((const float4*)in)[i];
        ((float4*)out)[i] = make_float4(tf32r(v.x), tf32r(v.y), tf32r(v.z), tf32r(v.w));
    }
}

__device__ __forceinline__ void mma_tf32(float c[4], const unsigned a[4], const unsigned b[2]) {
    asm volatile(
        "mma.sync.aligned.m16n8k8.row.col.f32.tf32.tf32.f32 "
        "{%0,%1,%2,%3}, {%4,%5,%6,%7}, {%8,%9}, {%0,%1,%2,%3};\n"
        : "+f"(c[0]), "+f"(c[1]), "+f"(c[2]), "+f"(c[3])
        : "r"(a[0]), "r"(a[1]), "r"(a[2]), "r"(a[3]), "r"(b[0]), "r"(b[1]));
}

__device__ __forceinline__ void ldsm_x4(unsigned r[4], const float* p) {
    unsigned addr = (unsigned)__cvta_generic_to_shared(p);
    asm volatile(
        "ldmatrix.sync.aligned.m8n8.x4.shared.b16 {%0,%1,%2,%3}, [%4];"
        : "=r"(r[0]), "=r"(r[1]), "=r"(r[2]), "=r"(r[3]) : "r"(addr));
}

__device__ __forceinline__ void cp_async16(void* smem, const void* gmem) {
    unsigned s = (unsigned)__cvta_generic_to_shared(smem);
    asm volatile("cp.async.cg.shared.global [%0], [%1], 16;" :: "r"(s), "l"(gmem));
}
#define CP_COMMIT() asm volatile("cp.async.commit_group;")
#define CP_WAIT0()  asm volatile("cp.async.wait_group 0;" ::: "memory")

// ---------------------------------------------------------------------------
// TF32 tensor-core GEMM with bias (R8 mainloop). ilv=1: store C interleaved-4.
// ---------------------------------------------------------------------------
#define BK   32
#define PADK 36
#define PADN 136
#define AS_STAGE (128 * PADK)
#define BS_STAGE (BK * PADN)
#define SMEM_FLOATS (2 * AS_STAGE + 2 * BS_STAGE)
#define SMEM_BYTES  (SMEM_FLOATS * 4)

__global__ void __launch_bounds__(256, 2) gemm_tf32_bias(
    const float* __restrict__ W, const float* __restrict__ X,
    const float* __restrict__ bias, float* __restrict__ C,
    int M, int N, int K, int ilv)
{
    extern __shared__ float smem[];
    float* const Abase = smem;
    float* const Bbase = smem + 2 * AS_STAGE;

    const int b  = blockIdx.z;
    const float* Xb = X + (size_t)b * K * N;
    float*       Cb = C + (size_t)b * M * N;
    const int m0 = blockIdx.y * 128;
    const int n0 = blockIdx.x * 128;
    const int tid  = threadIdx.x;
    const int lane = tid & 31;
    const int warp = tid >> 5;
    const int wm = (warp >> 2) * 64;
    const int wn = (warp & 3) * 32;
    const int g  = lane >> 2;
    const int t  = lane & 3;

    const int row_a = lane & 15;
    const int col_a = (lane >> 4) * 4;

    const int ar = tid & 127;
    const int akb = (tid >> 7) * 16;
    const int br = tid >> 5;
    const int bc = (tid & 31) * 4;

    const float* gA = &W[(size_t)(m0 + ar) * K + akb];
    const float* gB = &Xb[(size_t)br * N + n0 + bc];

    float acc[4][4][4];
#pragma unroll
    for (int i = 0; i < 4; ++i)
#pragma unroll
        for (int j = 0; j < 4; ++j)
#pragma unroll
            for (int r = 0; r < 4; ++r) acc[i][j][r] = 0.f;

    {
        float* sA = Abase + ar * PADK + akb;
        float* sB = Bbase + br * PADN + bc;
#pragma unroll
        for (int i = 0; i < 4; ++i)
            cp_async16(sA + i * 4, gA + i * 4);
#pragma unroll
        for (int j = 0; j < 4; ++j)
            cp_async16(sB + j * 8 * PADN, gB + (size_t)j * 8 * N);
    }
    CP_COMMIT();
    CP_WAIT0();
    __syncthreads();

    int cur = 0;
    for (int k0 = 0; k0 < K; k0 += BK) {
        const bool has_next = (k0 + BK < K);
        if (has_next) {
            const int nxt = cur ^ 1;
            float* sA = Abase + nxt * AS_STAGE + ar * PADK + akb;
            float* sB = Bbase + nxt * BS_STAGE + br * PADN + bc;
#pragma unroll
            for (int i = 0; i < 4; ++i)
                cp_async16(sA + i * 4, gA + k0 + BK + i * 4);
#pragma unroll
            for (int j = 0; j < 4; ++j)
                cp_async16(sB + j * 8 * PADN, gB + (size_t)(k0 + BK + j * 8) * N);
            CP_COMMIT();
        }

        const float* As = Abase + cur * AS_STAGE;
        const float* Bs = Bbase + cur * BS_STAGE;
#pragma unroll
        for (int kk = 0; kk < BK; kk += 8) {
            unsigned af[4][4], bf[4][2];
#pragma unroll
            for (int mt = 0; mt < 4; ++mt)
                ldsm_x4(af[mt], As + (wm + mt * 16 + row_a) * PADK + kk + col_a);
#pragma unroll
            for (int nt = 0; nt < 4; ++nt) {
                const int nb = wn + nt * 8;
                bf[nt][0] = __float_as_uint(Bs[(kk + t    ) * PADN + nb + g]);
                bf[nt][1] = __float_as_uint(Bs[(kk + t + 4) * PADN + nb + g]);
            }
#pragma unroll
            for (int mt = 0; mt < 4; ++mt)
#pragma unroll
                for (int nt = 0; nt < 4; ++nt)
                    mma_tf32(acc[mt][nt], af[mt], bf[nt]);
        }

        if (has_next) {
            CP_WAIT0();
            __syncthreads();
            cur ^= 1;
        }
    }

    if (ilv == 0) {
#pragma unroll
        for (int mt = 0; mt < 4; ++mt) {
#pragma unroll
            for (int rh = 0; rh < 2; ++rh) {
                const int m = m0 + wm + mt * 16 + g + rh * 8;
                const float bv = bias[m];
#pragma unroll
                for (int nt = 0; nt < 4; ++nt) {
                    float2 o;
                    o.x = acc[mt][nt][rh * 2 + 0] + bv;
                    o.y = acc[mt][nt][rh * 2 + 1] + bv;
                    *(float2*)&Cb[(size_t)m * N + n0 + wn + nt * 8 + t * 2] = o;
                }
            }
        }
    } else {
        // Interleaved-4: element (m, n) -> Cb[(m>>2)*4*N + n*4 + (m&3)]
#pragma unroll
        for (int mt = 0; mt < 4; ++mt) {
#pragma unroll
            for (int rh = 0; rh < 2; ++rh) {
                const int m = m0 + wm + mt * 16 + g + rh * 8;
                const float bv = bias[m];
                float* base = Cb + (size_t)(m >> 2) * 4 * N + (m & 3);
#pragma unroll
                for (int nt = 0; nt < 4; ++nt) {
                    const int n = n0 + wn + nt * 8 + t * 2;
                    base[(size_t)n * 4]       = acc[mt][nt][rh * 2 + 0] + bv;
                    base[(size_t)(n + 1) * 4] = acc[mt][nt][rh * 2 + 1] + bv;
                }
            }
        }
    }
}

// ---------------------------------------------------------------------------
// Fused multi-range neighborhood attention, float4 (interleaved) k/v loads.
// Per neighbor: 8 LDG.128 for k + 8 for v (vs 64 scalar LDG) — 4x fewer
// load instructions at identical coalescing (512B contiguous per inst).
// Output stays channel-major for the proj GEMM.
// ---------------------------------------------------------------------------
template<int KS, int DIL>
__device__ __forceinline__ void attend_range(
    const float* __restrict__ qb, const float* __restrict__ kb,
    const float* __restrict__ vb, const float* __restrict__ s_erpb,
    float* __restrict__ ob, int x, int y)
{
    const int idx = y * WIDTH + x;

    float q[32];
#pragma unroll
    for (int gi = 0; gi < 8; ++gi) {
        float4 qv = *(const float4*)&qb[(size_t)(gi * HW + idx) * 4];
        q[4 * gi + 0] = qv.x * 0.17677669529663687f;
        q[4 * gi + 1] = qv.y * 0.17677669529663687f;
        q[4 * gi + 2] = qv.z * 0.17677669529663687f;
        q[4 * gi + 3] = qv.w * 0.17677669529663687f;
    }

    float s = 0.f;
    float acc[32];
#pragma unroll
    for (int d = 0; d < 32; ++d) acc[d] = 0.f;

#pragma unroll 1
    for (int i = 0; i < KS; ++i) {
        const int ny = y + (i - KS / 2) * DIL;
        const bool iby = ((unsigned)ny < (unsigned)WIDTH);
#pragma unroll 1
        for (int j = 0; j < KS; ++j) {
            const int nx = x + (j - KS / 2) * DIL;
            const float erpb = s_erpb[i * KS + j];
            if (iby && ((unsigned)nx < (unsigned)WIDTH)) {
                const int nidx = ny * WIDTH + nx;

                float4 kk[8];
#pragma unroll
                for (int gi = 0; gi < 8; ++gi)
                    kk[gi] = *(const float4*)&kb[(size_t)(gi * HW + nidx) * 4];

                float d0 = q[0] * kk[0].x, d1 = q[1] * kk[0].y;
                float d2 = q[2] * kk[0].z, d3 = q[3] * kk[0].w;
#pragma unroll
                for (int gi = 1; gi < 8; ++gi) {
                    d0 += q[4 * gi + 0] * kk[gi].x;
                    d1 += q[4 * gi + 1] * kk[gi].y;
                    d2 += q[4 * gi + 2] * kk[gi].z;
                    d3 += q[4 * gi + 3] * kk[gi].w;
                }

                float4 vv[8];
#pragma unroll
                for (int gi = 0; gi < 8; ++gi)
                    vv[gi] = *(const float4*)&vb[(size_t)(gi * HW + nidx) * 4];

                const float dot = (d0 + d1) + (d2 + d3);
                const float p = __expf(dot) * erpb;
                s += p;
#pragma unroll
                for (int gi = 0; gi < 8; ++gi) {
                    acc[4 * gi + 0] += p * vv[gi].x;
                    acc[4 * gi + 1] += p * vv[gi].y;
                    acc[4 * gi + 2] += p * vv[gi].z;
                    acc[4 * gi + 3] += p * vv[gi].w;
                }
            } else {
                s += erpb;   // OOB: logit = rpb, v = 0
            }
        }
    }

    const float inv = 1.f / s;
#pragma unroll
    for (int d = 0; d < 32; ++d)
        ob[(size_t)d * HW + idx] = tf32r(acc[d] * inv);
}

__global__ void __launch_bounds__(256) attn_fused(
    const float* __restrict__ qkv,
    const float* __restrict__ rpb0, const float* __restrict__ rpb1,
    const float* __restrict__ rpb2, float* __restrict__ att)
{
    __shared__ float s_erpb[81];

    const int bh = blockIdx.z;
    const int b  = bh >> 3;
    const int h  = bh & 7;
    const int tid = threadIdx.y * 32 + threadIdx.x;

    if (h < 4) {
        if (tid < 25) s_erpb[tid] = __expf(rpb0[h * 25 + tid]);
    } else if (h < 7) {
        if (tid < 49) s_erpb[tid] = __expf(rpb1[(h - 4) * 49 + tid]);
    } else {
        if (tid < 81) s_erpb[tid] = __expf(rpb2[tid]);
    }
    __syncthreads();

    const int x = blockIdx.x * 32 + threadIdx.x;
    const int y = blockIdx.y * 8 + threadIdx.y;

    // Interleaved layout: q groups 8h.., k groups 64+8h.., v groups 128+8h..
    const float* qb = qkv + ((size_t)b * 192 +       h * 8) * HW * 4;
    const float* kb = qkv + ((size_t)b * 192 +  64 + h * 8) * HW * 4;
    const float* vb = qkv + ((size_t)b * 192 + 128 + h * 8) * HW * 4;
    float* ob = att + ((size_t)b * 256 + h * 32) * HW;

    if (h < 4)       attend_range<5, 1>(qb, kb, vb, s_erpb, ob, x, y);
    else if (h < 7)  attend_range<7, 2>(qb, kb, vb, s_erpb, ob, x, y);
    else             attend_range<9, 3>(qb, kb, vb, s_erpb, ob, x, y);
}

// ---------------------------------------------------------------------------
extern "C" void kernel_launch(void* const* d_in, const int* in_sizes, int n_in,
                              void* d_out, int out_size)
{
    const float* x      = (const float*)d_in[0];
    const float* qkv_w  = (const float*)d_in[1];
    const float* qkv_b  = (const float*)d_in[2];
    const float* proj_w = (const float*)d_in[3];
    const float* proj_b = (const float*)d_in[4];
    const float* rpb0   = (const float*)d_in[5];
    const float* rpb1   = (const float*)d_in[6];
    const float* rpb2   = (const float*)d_in[7];
    float* out = (float*)d_out;

    float *qkv_ptr, *att_ptr, *xr_ptr, *wqkv_ptr, *wproj_ptr;
    cudaGetSymbolAddress((void**)&qkv_ptr,  g_qkv);
    cudaGetSymbolAddress((void**)&att_ptr,  g_att);
    cudaGetSymbolAddress((void**)&xr_ptr,   g_xr);
    cudaGetSymbolAddress((void**)&wqkv_ptr, g_wqkv);
    cudaGetSymbolAddress((void**)&wproj_ptr,g_wproj);

    static bool attr_set = false;
    if (!attr_set) {
        cudaFuncSetAttribute(gemm_tf32_bias,
                             cudaFuncAttributeMaxDynamicSharedMemorySize, SMEM_BYTES);
        attr_set = true;
    }

    // 0) Pre-round GEMM inputs to tf32
    round_tf32_copy<<<(BATCH * 256 * HW / 4 + 255) / 256, 256>>>(x, xr_ptr, BATCH * 256 * HW / 4);
    round_tf32_copy<<<(768 * 256 / 4 + 255) / 256, 256>>>(qkv_w, wqkv_ptr, 768 * 256 / 4);
    round_tf32_copy<<<(256 * 256 / 4 + 255) / 256, 256>>>(proj_w, wproj_ptr, 256 * 256 / 4);

    // 1) QKV projection — TF32 tensor cores, interleaved-4 output
    gemm_tf32_bias<<<dim3(32, 6, BATCH), 256, SMEM_BYTES>>>(wqkv_ptr, xr_ptr, qkv_b, qkv_ptr, 768, HW, 256, 1);

    // 2) Fused multi-range neighborhood attention (float4 k/v loads)
    attn_fused<<<dim3(2, 8, BATCH * 8), dim3(32, 8)>>>(qkv_ptr, rpb0, rpb1, rpb2, att_ptr);

    // 3) Output projection — TF32 tensor cores, standard output
    gemm_tf32_bias<<<dim3(32, 2, BATCH), 256, SMEM_BYTES>>>(wproj_ptr, att_ptr, proj_b, out, 256, HW, 256, 0);
}

// round 11
// speedup vs baseline: 1.3499x; 1.3499x over previous
#include <cuda_runtime.h>
#include <math.h>

// Problem constants
#define HW    4096
#define WIDTH 64
#define BATCH 4

// Scratch (device globals — no allocation allowed in kernel_launch)
static __device__ float g_qkv[(size_t)BATCH * 768 * HW];   // (B,768,HW) channel-major
static __device__ float g_att[(size_t)BATCH * 256 * HW];   // (B,256,HW), tf32-rounded at store
static __device__ float g_xr[(size_t)BATCH * 256 * HW];    // tf32-rounded x
static __device__ float g_wqkv[768 * 256];                 // tf32-rounded qkv_w
static __device__ float g_wproj[256 * 256];                // tf32-rounded proj_w

// ---------------------------------------------------------------------------
__device__ __forceinline__ float tf32r(float x) {
    unsigned u;
    asm("cvt.rna.tf32.f32 %0, %1;" : "=r"(u) : "f"(x));
    return __uint_as_float(u);
}

// One launch rounds all three GEMM inputs (x, qkv_w, proj_w) to tf32.
#define NX4   (BATCH * 256 * HW / 4)
#define NW1_4 (768 * 256 / 4)
#define NW2_4 (256 * 256 / 4)
__global__ void round_all_tf32(const float* __restrict__ x,
                               const float* __restrict__ w1,
                               const float* __restrict__ w2,
                               float* __restrict__ xo,
                               float* __restrict__ w1o,
                               float* __restrict__ w2o)
{
    int i = blockIdx.x * blockDim.x + threadIdx.x;
    const float4* in; float4* out; int idx;
    if (i < NX4)                { in = (const float4*)x;  out = (float4*)xo;  idx = i; }
    else if (i < NX4 + NW1_4)   { in = (const float4*)w1; out = (float4*)w1o; idx = i - NX4; }
    else if (i < NX4 + NW1_4 + NW2_4) { in = (const float4*)w2; out = (float4*)w2o; idx = i - NX4 - NW1_4; }
    else return;
    float4 v = in[idx];
    out[idx] = make_float4(tf32r(v.x), tf32r(v.y), tf32r(v.z), tf32r(v.w));
}

__device__ __forceinline__ void mma_tf32(float c[4], const unsigned a[4], const unsigned b[2]) {
    asm volatile(
        "mma.sync.aligned.m16n8k8.row.col.f32.tf32.tf32.f32 "
        "{%0,%1,%2,%3}, {%4,%5,%6,%7}, {%8,%9}, {%0,%1,%2,%3};\n"
        : "+f"(c[0]), "+f"(c[1]), "+f"(c[2]), "+f"(c[3])
        : "r"(a[0]), "r"(a[1]), "r"(a[2]), "r"(a[3]), "r"(b[0]), "r"(b[1]));
}

__device__ __forceinline__ void ldsm_x4(unsigned r[4], const float* p) {
    unsigned addr = (unsigned)__cvta_generic_to_shared(p);
    asm volatile(
        "ldmatrix.sync.aligned.m8n8.x4.shared.b16 {%0,%1,%2,%3}, [%4];"
        : "=r"(r[0]), "=r"(r[1]), "=r"(r[2]), "=r"(r[3]) : "r"(addr));
}

__device__ __forceinline__ void cp_async16(void* smem, const void* gmem) {
    unsigned s = (unsigned)__cvta_generic_to_shared(smem);
    asm volatile("cp.async.cg.shared.global [%0], [%1], 16;" :: "r"(s), "l"(gmem));
}
#define CP_COMMIT() asm volatile("cp.async.commit_group;")
#define CP_WAIT0()  asm volatile("cp.async.wait_group 0;" ::: "memory")
#define CP_WAIT1()  asm volatile("cp.async.wait_group 1;" ::: "memory")

// ---------------------------------------------------------------------------
// TF32 tensor-core GEMM with bias, 3-stage cp.async pipeline.
// Block 128x128x32, 8 warps, warp tile 64x32 (4x4 m16n8k8 frags).
// A staged [m][k] PADK=36 (ldmatrix conflict-free); B staged [k][n] PADN=136.
// ---------------------------------------------------------------------------
#define BK   32
#define PADK 36
#define PADN 136
#define AS_STAGE (128 * PADK)
#define BS_STAGE (BK * PADN)
#define SMEM_FLOATS (3 * AS_STAGE + 3 * BS_STAGE)
#define SMEM_BYTES  (SMEM_FLOATS * 4)

__global__ void __launch_bounds__(256, 2) gemm_tf32_bias(
    const float* __restrict__ W, const float* __restrict__ X,
    const float* __restrict__ bias, float* __restrict__ C,
    int M, int N, int K)
{
    extern __shared__ float smem[];
    float* const Abase = smem;
    float* const Bbase = smem + 3 * AS_STAGE;

    const int b  = blockIdx.z;
    const float* Xb = X + (size_t)b * K * N;
    float*       Cb = C + (size_t)b * M * N;
    const int m0 = blockIdx.y * 128;
    const int n0 = blockIdx.x * 128;
    const int tid  = threadIdx.x;
    const int lane = tid & 31;
    const int warp = tid >> 5;
    const int wm = (warp >> 2) * 64;
    const int wn = (warp & 3) * 32;
    const int g  = lane >> 2;
    const int t  = lane & 3;

    const int row_a = lane & 15;
    const int col_a = (lane >> 4) * 4;

    const int ar = tid & 127;
    const int akb = (tid >> 7) * 16;
    const int br = tid >> 5;
    const int bc = (tid & 31) * 4;

    const float* gA = &W[(size_t)(m0 + ar) * K + akb];
    const float* gB = &Xb[(size_t)br * N + n0 + bc];

    float acc[4][4][4];
#pragma unroll
    for (int i = 0; i < 4; ++i)
#pragma unroll
        for (int j = 0; j < 4; ++j)
#pragma unroll
            for (int r = 0; r < 4; ++r) acc[i][j][r] = 0.f;

    // Prologue: stages 0 and 1 in flight
#pragma unroll
    for (int st = 0; st < 2; ++st) {
        float* sA = Abase + st * AS_STAGE + ar * PADK + akb;
        float* sB = Bbase + st * BS_STAGE + br * PADN + bc;
        const int ko = st * BK;
#pragma unroll
        for (int i = 0; i < 4; ++i)
            cp_async16(sA + i * 4, gA + ko + i * 4);
#pragma unroll
        for (int j = 0; j < 4; ++j)
            cp_async16(sB + j * 8 * PADN, gB + (size_t)(ko + j * 8) * N);
        CP_COMMIT();
    }
    CP_WAIT1();      // stage 0 ready
    __syncthreads();

    int cur = 0;
    for (int k0 = 0; k0 < K; k0 += BK) {
        const float* As = Abase + cur * AS_STAGE;
        const float* Bs = Bbase + cur * BS_STAGE;
#pragma unroll
        for (int kk = 0; kk < BK; kk += 8) {
            unsigned af[4][4], bf[4][2];
#pragma unroll
            for (int mt = 0; mt < 4; ++mt)
                ldsm_x4(af[mt], As + (wm + mt * 16 + row_a) * PADK + kk + col_a);
#pragma unroll
            for (int nt = 0; nt < 4; ++nt) {
                const int nb = wn + nt * 8;
                bf[nt][0] = __float_as_uint(Bs[(kk + t    ) * PADN + nb + g]);
                bf[nt][1] = __float_as_uint(Bs[(kk + t + 4) * PADN + nb + g]);
            }
#pragma unroll
            for (int mt = 0; mt < 4; ++mt)
#pragma unroll
                for (int nt = 0; nt < 4; ++nt)
                    mma_tf32(acc[mt][nt], af[mt], bf[nt]);
        }

        if (k0 + BK < K) {
            const int k2 = k0 + 2 * BK;
            if (k2 < K) {
                const int st = (cur + 2) % 3;
                float* sA = Abase + st * AS_STAGE + ar * PADK + akb;
                float* sB = Bbase + st * BS_STAGE + br * PADN + bc;
#pragma unroll
                for (int i = 0; i < 4; ++i)
                    cp_async16(sA + i * 4, gA + k2 + i * 4);
#pragma unroll
                for (int j = 0; j < 4; ++j)
                    cp_async16(sB + j * 8 * PADN, gB + (size_t)(k2 + j * 8) * N);
                CP_COMMIT();
                CP_WAIT1();   // next stage (cur+1) ready
            } else {
                CP_WAIT0();   // drain: only cur+1 outstanding
            }
            __syncthreads();
            cur = (cur + 1) % 3;
        }
    }

    // Epilogue: c0,c1 = row g, cols 2t,2t+1; c2,c3 = row g+8
#pragma unroll
    for (int mt = 0; mt < 4; ++mt) {
#pragma unroll
        for (int rh = 0; rh < 2; ++rh) {
            const int m = m0 + wm + mt * 16 + g + rh * 8;
            const float bv = bias[m];
#pragma unroll
            for (int nt = 0; nt < 4; ++nt) {
                float2 o;
                o.x = acc[mt][nt][rh * 2 + 0] + bv;
                o.y = acc[mt][nt][rh * 2 + 1] + bv;
                *(float2*)&Cb[(size_t)m * N + n0 + wn + nt * 8 + t * 2] = o;
            }
        }
    }
}

// ---------------------------------------------------------------------------
// Fused multi-range neighborhood attention (R8 winner, reverted verbatim).
// ---------------------------------------------------------------------------
template<int KS, int DIL>
__device__ __forceinline__ void attend_range(
    const float* __restrict__ qb, const float* __restrict__ kb,
    const float* __restrict__ vb, const float* __restrict__ s_erpb,
    float* __restrict__ ob, int x, int y)
{
    const int idx = y * WIDTH + x;

    float q[32];
#pragma unroll
    for (int d = 0; d < 32; ++d)
        q[d] = qb[(size_t)d * HW + idx] * 0.17677669529663687f;  // 32^-0.5

    float s = 0.f;
    float acc[32];
#pragma unroll
    for (int d = 0; d < 32; ++d) acc[d] = 0.f;

#pragma unroll 1
    for (int i = 0; i < KS; ++i) {
        const int ny = y + (i - KS / 2) * DIL;
        const bool iby = ((unsigned)ny < (unsigned)WIDTH);
#pragma unroll 1
        for (int j = 0; j < KS; ++j) {
            const int nx = x + (j - KS / 2) * DIL;
            const float erpb = s_erpb[i * KS + j];
            if (iby && ((unsigned)nx < (unsigned)WIDTH)) {
                const int nidx = ny * WIDTH + nx;
                float dot = 0.f;
#pragma unroll
                for (int d = 0; d < 32; ++d)
                    dot += q[d] * kb[(size_t)d * HW + nidx];
                const float p = __expf(dot) * erpb;
                s += p;
#pragma unroll
                for (int d = 0; d < 32; ++d)
                    acc[d] += p * vb[(size_t)d * HW + nidx];
            } else {
                s += erpb;   // OOB: logit = rpb, v = 0
            }
        }
    }

    const float inv = 1.f / s;
#pragma unroll
    for (int d = 0; d < 32; ++d)
        ob[(size_t)d * HW + idx] = tf32r(acc[d] * inv);
}

__global__ void __launch_bounds__(256, 2) attn_fused(
    const float* __restrict__ qkv,
    const float* __restrict__ rpb0, const float* __restrict__ rpb1,
    const float* __restrict__ rpb2, float* __restrict__ att)
{
    __shared__ float s_erpb[81];

    const int bh = blockIdx.z;
    const int b  = bh >> 3;
    const int h  = bh & 7;
    const int tid = threadIdx.y * 32 + threadIdx.x;

    if (h < 4) {
        if (tid < 25) s_erpb[tid] = __expf(rpb0[h * 25 + tid]);
    } else if (h < 7) {
        if (tid < 49) s_erpb[tid] = __expf(rpb1[(h - 4) * 49 + tid]);
    } else {
        if (tid < 81) s_erpb[tid] = __expf(rpb2[tid]);
    }
    __syncthreads();

    const int x = blockIdx.x * 32 + threadIdx.x;
    const int y = blockIdx.y * 8 + threadIdx.y;

    const float* qb = qkv + ((size_t)b * 768 + h * 32) * HW;
    const float* kb = qb + (size_t)256 * HW;
    const float* vb = qb + (size_t)512 * HW;
    float* ob = att + ((size_t)b * 256 + h * 32) * HW;

    if (h < 4)       attend_range<5, 1>(qb, kb, vb, s_erpb, ob, x, y);
    else if (h < 7)  attend_range<7, 2>(qb, kb, vb, s_erpb, ob, x, y);
    else             attend_range<9, 3>(qb, kb, vb, s_erpb, ob, x, y);
}

// ---------------------------------------------------------------------------
extern "C" void kernel_launch(void* const* d_in, const int* in_sizes, int n_in,
                              void* d_out, int out_size)
{
    const float* x      = (const float*)d_in[0];
    const float* qkv_w  = (const float*)d_in[1];
    const float* qkv_b  = (const float*)d_in[2];
    const float* proj_w = (const float*)d_in[3];
    const float* proj_b = (const float*)d_in[4];
    const float* rpb0   = (const float*)d_in[5];
    const float* rpb1   = (const float*)d_in[6];
    const float* rpb2   = (const float*)d_in[7];
    float* out = (float*)d_out;

    float *qkv_ptr, *att_ptr, *xr_ptr, *wqkv_ptr, *wproj_ptr;
    cudaGetSymbolAddress((void**)&qkv_ptr,  g_qkv);
    cudaGetSymbolAddress((void**)&att_ptr,  g_att);
    cudaGetSymbolAddress((void**)&xr_ptr,   g_xr);
    cudaGetSymbolAddress((void**)&wqkv_ptr, g_wqkv);
    cudaGetSymbolAddress((void**)&wproj_ptr,g_wproj);

    static bool attr_set = false;
    if (!attr_set) {
        cudaFuncSetAttribute(gemm_tf32_bias,
                             cudaFuncAttributeMaxDynamicSharedMemorySize, SMEM_BYTES);
        attr_set = true;
    }

    // 0) Pre-round all GEMM inputs to tf32 in one launch
    {
        const int total = NX4 + NW1_4 + NW2_4;
        round_all_tf32<<<(total + 255) / 256, 256>>>(x, qkv_w, proj_w,
                                                     xr_ptr, wqkv_ptr, wproj_ptr);
    }

    // 1) QKV projection — TF32 tensor cores, 3-stage pipeline
    gemm_tf32_bias<<<dim3(32, 6, BATCH), 256, SMEM_BYTES>>>(wqkv_ptr, xr_ptr, qkv_b, qkv_ptr, 768, HW, 256);

    // 2) Fused multi-range neighborhood attention (R8 winner)
    attn_fused<<<dim3(2, 8, BATCH * 8), dim3(32, 8)>>>(qkv_ptr, rpb0, rpb1, rpb2, att_ptr);

    // 3) Output projection — TF32 tensor cores, 3-stage pipeline
    gemm_tf32_bias<<<dim3(32, 2, BATCH), 256, SMEM_BYTES>>>(wproj_ptr, att_ptr, proj_b, out, 256, HW, 256);
}